// round 3
// baseline (speedup 1.0000x reference)
#include <cuda_runtime.h>
#include <cuda_bf16.h>
#include <math.h>

// Problem constants: B=2, S=4096, H=1024, NH=16, hd=64
#define BATCH 2
#define SEQ   4096
#define HID   1024
#define NHEAD 16
#define HDIM  64
#define TOKENS (BATCH*SEQ)          // 8192
#define QKVW  (3*HID)               // 3072

// ---------------- device scratch (no allocations allowed) ----------------
__device__ float g_qkv[(size_t)TOKENS * QKVW];   // 8192 x 3072
__device__ float g_q  [(size_t)TOKENS * HID];    // [B][NH][S][hd]
__device__ float g_k  [(size_t)TOKENS * HID];    // [B][NH][S][hd]
__device__ float g_o  [(size_t)TOKENS * HID];    // [B][S][H] attention out

// ---------------- generic fp32 tiled GEMM: C = A(MxK) @ B(KxN) ----------------
// BM=BN=128, BK=8, 256 threads, 8x8 microtile per thread.
__global__ void gemm128_kernel(const float* __restrict__ A,
                               const float* __restrict__ B,
                               float* __restrict__ C,
                               int M, int N, int K)
{
    __shared__ float As[8][128];   // [k][m]
    __shared__ float Bs[8][128];   // [k][n]

    const int tid  = threadIdx.x;
    const int brow = blockIdx.y;   // M tile
    const int bcol = blockIdx.x;   // N tile
    const int row  = tid >> 4;     // 0..15
    const int col  = tid & 15;     // 0..15

    const int aRow = tid >> 1;           // 0..127
    const int aCol = (tid & 1) * 4;      // 0 or 4
    const int bRow = tid >> 5;           // 0..7
    const int bCol = (tid & 31) * 4;     // 0..124

    const float* Ag = A + (size_t)(brow * 128 + aRow) * K + aCol;
    const float* Bg = B + (size_t)bRow * N + bcol * 128 + bCol;

    float acc[8][8];
#pragma unroll
    for (int i = 0; i < 8; i++)
#pragma unroll
        for (int j = 0; j < 8; j++) acc[i][j] = 0.f;

    for (int k0 = 0; k0 < K; k0 += 8) {
        float4 a4 = *(const float4*)(Ag + k0);
        float4 b4 = *(const float4*)(Bg + (size_t)k0 * N);
        As[aCol + 0][aRow] = a4.x;
        As[aCol + 1][aRow] = a4.y;
        As[aCol + 2][aRow] = a4.z;
        As[aCol + 3][aRow] = a4.w;
        *(float4*)&Bs[bRow][bCol] = b4;
        __syncthreads();

#pragma unroll
        for (int kk = 0; kk < 8; kk++) {
            float4 ra0 = *(const float4*)&As[kk][row * 8];
            float4 ra1 = *(const float4*)&As[kk][row * 8 + 4];
            float4 rb0 = *(const float4*)&Bs[kk][col * 8];
            float4 rb1 = *(const float4*)&Bs[kk][col * 8 + 4];
            float ra[8] = {ra0.x, ra0.y, ra0.z, ra0.w, ra1.x, ra1.y, ra1.z, ra1.w};
            float rb[8] = {rb0.x, rb0.y, rb0.z, rb0.w, rb1.x, rb1.y, rb1.z, rb1.w};
#pragma unroll
            for (int i = 0; i < 8; i++)
#pragma unroll
                for (int j = 0; j < 8; j++)
                    acc[i][j] += ra[i] * rb[j];
        }
        __syncthreads();
    }

    // write out
#pragma unroll
    for (int i = 0; i < 8; i++) {
        float* Cg = C + (size_t)(brow * 128 + row * 8 + i) * N + bcol * 128 + col * 8;
        *(float4*)(Cg)     = make_float4(acc[i][0], acc[i][1], acc[i][2], acc[i][3]);
        *(float4*)(Cg + 4) = make_float4(acc[i][4], acc[i][5], acc[i][6], acc[i][7]);
    }
}

// ---------------- fused per-head RMSNorm + RoPE ----------------
// One warp per (token, head). Lane l owns dims l and l+32.
__global__ void rmsnorm_rope_kernel(const float* __restrict__ qkv,
                                    const float* __restrict__ cosb,
                                    const float* __restrict__ sinb,
                                    const float* __restrict__ gq,
                                    const float* __restrict__ gk,
                                    float* __restrict__ qout,
                                    float* __restrict__ kout)
{
    int warp = (blockIdx.x * blockDim.x + threadIdx.x) >> 5;
    int lane = threadIdx.x & 31;
    if (warp >= TOKENS * NHEAD) return;
    int t = warp / NHEAD;           // global token 0..8191
    int h = warp % NHEAD;
    int s = t & (SEQ - 1);          // position within sequence
    int b = t / SEQ;

    const float* qp = qkv + (size_t)t * QKVW + h * HDIM;
    const float* kp = qp + HID;

    float q0 = qp[lane], q1 = qp[lane + 32];
    float k0 = kp[lane], k1 = kp[lane + 32];

    float sq = q0 * q0 + q1 * q1;
    float sk = k0 * k0 + k1 * k1;
#pragma unroll
    for (int off = 16; off; off >>= 1) {
        sq += __shfl_xor_sync(0xffffffffu, sq, off);
        sk += __shfl_xor_sync(0xffffffffu, sk, off);
    }
    float rq = rsqrtf(sq * (1.0f / HDIM) + 1e-6f);
    float rk = rsqrtf(sk * (1.0f / HDIM) + 1e-6f);
    q0 *= rq * gq[lane];  q1 *= rq * gq[lane + 32];
    k0 *= rk * gk[lane];  k1 *= rk * gk[lane + 32];

    float c0 = cosb[(size_t)s * HDIM + lane];
    float c1 = cosb[(size_t)s * HDIM + lane + 32];
    float s0 = sinb[(size_t)s * HDIM + lane];
    float s1 = sinb[(size_t)s * HDIM + lane + 32];

    // out[d] = x[d]*cos[d] - x[d+32]*sin[d];  out[d+32] = x[d+32]*cos[d+32] + x[d]*sin[d+32]
    float qo0 = q0 * c0 - q1 * s0;
    float qo1 = q1 * c1 + q0 * s1;
    float ko0 = k0 * c0 - k1 * s0;
    float ko1 = k1 * c1 + k0 * s1;

    size_t base = (((size_t)(b * NHEAD + h)) * SEQ + s) * HDIM;
    qout[base + lane]      = qo0;
    qout[base + lane + 32] = qo1;
    kout[base + lane]      = ko0;
    kout[base + lane + 32] = ko1;
}

// ---------------- causal flash attention (fp32, 64x64 tiles) ----------------
// grid: (S/64, B*NH). 256 threads = 16x16 microgrid, each thread 4x4.
// Shared: Qs[d][r] (transposed), Ks[d][c] (transposed), Vs[j][c].
// P tile (post-softmax, transposed [j][r]) ALIASES Ks (K no longer needed then).
#define APAD 68   // row stride in floats (16B-aligned, shifts banks per row)
__global__ void flash_attn_kernel(const float* __restrict__ Q,
                                  const float* __restrict__ K,
                                  const float* __restrict__ qkv,
                                  float* __restrict__ O)
{
    extern __shared__ float sm[];
    float (*Qs)[APAD] = (float(*)[APAD])sm;
    float (*Ks)[APAD] = (float(*)[APAD])(sm + 64 * APAD);
    float (*Vs)[APAD] = (float(*)[APAD])(sm + 2 * 64 * APAD);
    float (*Ps)[APAD] = Ks;  // alias: P overwrites K after S is computed

    const int tid = threadIdx.x;
    const int ty = tid >> 4;   // 0..15 -> rows 4ty..4ty+3
    const int tx = tid & 15;   // 0..15 -> cols 4tx..4tx+3
    const int bh = blockIdx.y;
    const int b = bh >> 4, h = bh & 15;
    const int qtile = blockIdx.x;

    const float* Qg = Q + ((size_t)bh * SEQ + qtile * 64) * HDIM;
    const float* Kg = K + (size_t)bh * SEQ * HDIM;
    const float* Vg = qkv + (size_t)b * SEQ * QKVW + 2 * HID + h * HDIM;

    // load Q tile transposed: Qs[d][r]
    {
        int r = tid >> 2;
        int dbase = (tid & 3) * 16;
        const float* qg = Qg + (size_t)r * HDIM + dbase;
#pragma unroll
        for (int i = 0; i < 16; i += 4) {
            float4 v = *(const float4*)(qg + i);
            Qs[dbase + i + 0][r] = v.x;
            Qs[dbase + i + 1][r] = v.y;
            Qs[dbase + i + 2][r] = v.z;
            Qs[dbase + i + 3][r] = v.w;
        }
    }

    float acc[4][4];
    float m_i[4], l_i[4];
#pragma unroll
    for (int i = 0; i < 4; i++) {
        m_i[i] = -INFINITY; l_i[i] = 0.f;
#pragma unroll
        for (int j = 0; j < 4; j++) acc[i][j] = 0.f;
    }
    const float scale = 0.125f;  // 1/sqrt(64)

    for (int kt = 0; kt <= qtile; kt++) {
        __syncthreads();  // prior PV done; Q stores visible on first iter
        // load K tile transposed + V tile direct
        {
            int r = tid >> 2;
            int dbase = (tid & 3) * 16;
            const float* kg = Kg + (size_t)(kt * 64 + r) * HDIM + dbase;
#pragma unroll
            for (int i = 0; i < 16; i += 4) {
                float4 v = *(const float4*)(kg + i);
                Ks[dbase + i + 0][r] = v.x;
                Ks[dbase + i + 1][r] = v.y;
                Ks[dbase + i + 2][r] = v.z;
                Ks[dbase + i + 3][r] = v.w;
            }
            const float* vg = Vg + (size_t)(kt * 64 + r) * QKVW + dbase;
#pragma unroll
            for (int i = 0; i < 16; i += 4) {
                *(float4*)&Vs[r][dbase + i] = *(const float4*)(vg + i);
            }
        }
        __syncthreads();

        // S = (Q K^T) * scale
        float sv[4][4];
#pragma unroll
        for (int i = 0; i < 4; i++)
#pragma unroll
            for (int j = 0; j < 4; j++) sv[i][j] = 0.f;

#pragma unroll 4
        for (int d = 0; d < 64; d++) {
            float rq[4];
            rq[0] = Qs[d][ty * 4 + 0]; rq[1] = Qs[d][ty * 4 + 1];
            rq[2] = Qs[d][ty * 4 + 2]; rq[3] = Qs[d][ty * 4 + 3];
            float4 rk = *(const float4*)&Ks[d][tx * 4];
            float rkk[4] = {rk.x, rk.y, rk.z, rk.w};
#pragma unroll
            for (int i = 0; i < 4; i++)
#pragma unroll
                for (int j = 0; j < 4; j++)
                    sv[i][j] += rq[i] * rkk[j];
        }

        const bool diag = (kt == qtile);
#pragma unroll
        for (int i = 0; i < 4; i++)
#pragma unroll
            for (int j = 0; j < 4; j++) {
                sv[i][j] *= scale;
                if (diag && (tx * 4 + j > ty * 4 + i)) sv[i][j] = -INFINITY;
            }

        // row max over the 16 column-threads
        float rmax[4];
#pragma unroll
        for (int i = 0; i < 4; i++) {
            float m = fmaxf(fmaxf(sv[i][0], sv[i][1]), fmaxf(sv[i][2], sv[i][3]));
#pragma unroll
            for (int off = 8; off; off >>= 1)
                m = fmaxf(m, __shfl_xor_sync(0xffffffffu, m, off));
            rmax[i] = m;
        }

        float alpha[4], rsum[4];
#pragma unroll
        for (int i = 0; i < 4; i++) {
            float mnew = fmaxf(m_i[i], rmax[i]);
            alpha[i] = __expf(m_i[i] - mnew);   // exp(-inf)=0 on first tile
            m_i[i] = mnew;
            float rs = 0.f;
#pragma unroll
            for (int j = 0; j < 4; j++) {
                float p = __expf(sv[i][j] - mnew);
                sv[i][j] = p;
                rs += p;
            }
            rsum[i] = rs;
        }
#pragma unroll
        for (int i = 0; i < 4; i++) {
#pragma unroll
            for (int off = 8; off; off >>= 1)
                rsum[i] += __shfl_xor_sync(0xffffffffu, rsum[i], off);
            l_i[i] = l_i[i] * alpha[i] + rsum[i];
#pragma unroll
            for (int j = 0; j < 4; j++) acc[i][j] *= alpha[i];
        }

        __syncthreads();  // all threads done reading Ks before P overwrites it
        // store P transposed: Ps[j_key][r]
#pragma unroll
        for (int i = 0; i < 4; i++)
#pragma unroll
            for (int j = 0; j < 4; j++)
                Ps[tx * 4 + j][ty * 4 + i] = sv[i][j];
        __syncthreads();

        // O += P @ V
#pragma unroll 4
        for (int j = 0; j < 64; j++) {
            float rp[4];
            rp[0] = Ps[j][ty * 4 + 0]; rp[1] = Ps[j][ty * 4 + 1];
            rp[2] = Ps[j][ty * 4 + 2]; rp[3] = Ps[j][ty * 4 + 3];
            float4 rv = *(const float4*)&Vs[j][tx * 4];
            float rvv[4] = {rv.x, rv.y, rv.z, rv.w};
#pragma unroll
            for (int i = 0; i < 4; i++)
#pragma unroll
                for (int jj = 0; jj < 4; jj++)
                    acc[i][jj] += rp[i] * rvv[jj];
        }
    }

    // epilogue: normalize and write to (B,S,H) layout for the output GEMM
#pragma unroll
    for (int i = 0; i < 4; i++) {
        float inv = 1.0f / l_i[i];
        size_t t = (size_t)b * SEQ + qtile * 64 + ty * 4 + i;
        float* og = O + t * HID + h * HDIM + tx * 4;
        og[0] = acc[i][0] * inv;
        og[1] = acc[i][1] * inv;
        og[2] = acc[i][2] * inv;
        og[3] = acc[i][3] * inv;
    }
}

// ---------------- launch ----------------
extern "C" void kernel_launch(void* const* d_in, const int* in_sizes, int n_in,
                              void* d_out, int out_size)
{
    const float* hs    = (const float*)d_in[0];  // (2,4096,1024)
    const float* rcos  = (const float*)d_in[1];  // (1,4096,64)
    const float* rsin  = (const float*)d_in[2];  // (1,4096,64)
    const float* Wqkv  = (const float*)d_in[3];  // (1024,3072)
    const float* Wo    = (const float*)d_in[4];  // (1024,1024)
    const float* gq    = (const float*)d_in[5];  // (64,)
    const float* gk    = (const float*)d_in[6];  // (64,)
    float* out = (float*)d_out;                  // (2,4096,1024)

    float *qkv_p, *q_p, *k_p, *o_p;
    cudaGetSymbolAddress((void**)&qkv_p, g_qkv);
    cudaGetSymbolAddress((void**)&q_p,   g_q);
    cudaGetSymbolAddress((void**)&k_p,   g_k);
    cudaGetSymbolAddress((void**)&o_p,   g_o);

    static bool attr_set = false;
    const int SMEM = 3 * 64 * APAD * (int)sizeof(float);  // 52224 B
    if (!attr_set) {
        cudaFuncSetAttribute(flash_attn_kernel,
                             cudaFuncAttributeMaxDynamicSharedMemorySize, SMEM);
        attr_set = true;
    }

    // 1. QKV = hidden_states @ W_qkv    (8192x1024 @ 1024x3072)
    gemm128_kernel<<<dim3(QKVW / 128, TOKENS / 128), 256>>>(hs, Wqkv, qkv_p,
                                                            TOKENS, QKVW, HID);
    // 2. per-head RMSNorm + RoPE -> g_q, g_k in [B][NH][S][hd]
    {
        int nwarps = TOKENS * NHEAD;          // 131072
        int blocks = nwarps / 8;              // 256 thr = 8 warps / block
        rmsnorm_rope_kernel<<<blocks, 256>>>(qkv_p, rcos, rsin, gq, gk, q_p, k_p);
    }
    // 3. causal flash attention -> g_o in (B,S,H)
    flash_attn_kernel<<<dim3(SEQ / 64, BATCH * NHEAD), 256, SMEM>>>(q_p, k_p, qkv_p, o_p);
    // 4. out = g_o @ W_o                (8192x1024 @ 1024x1024)
    gemm128_kernel<<<dim3(HID / 128, TOKENS / 128), 256>>>(o_p, Wo, out,
                                                           TOKENS, HID, HID);
}

// round 4
// speedup vs baseline: 1.6927x; 1.6927x over previous
#include <cuda_runtime.h>
#include <math.h>

// Problem constants: B=2, S=4096, H=1024, NH=16, hd=64
#define BATCH 2
#define SEQ   4096
#define HID   1024
#define NHEAD 16
#define HDIM  64
#define TOKENS (BATCH*SEQ)          // 8192
#define QKVW  (3*HID)               // 3072

// ---------------- device scratch (no allocations allowed) ----------------
__device__ float g_qkv[(size_t)TOKENS * QKVW];
__device__ float g_q  [(size_t)TOKENS * HID];    // [B][NH][S][hd]
__device__ float g_k  [(size_t)TOKENS * HID];    // [B][NH][S][hd]
__device__ float g_o  [(size_t)TOKENS * HID];    // [B][S][H]

// ---------------- tf32 helpers ----------------
__device__ __forceinline__ unsigned f2tf(float f) {
    unsigned u; asm("cvt.rna.tf32.f32 %0, %1;" : "=r"(u) : "f"(f)); return u;
}
__device__ __forceinline__ void mma8(float (&c)[4],
                                     unsigned a0, unsigned a1, unsigned a2, unsigned a3,
                                     unsigned b0, unsigned b1) {
    asm volatile(
        "mma.sync.aligned.m16n8k8.row.col.f32.tf32.tf32.f32 "
        "{%0,%1,%2,%3},{%4,%5,%6,%7},{%8,%9},{%0,%1,%2,%3};\n"
        : "+f"(c[0]), "+f"(c[1]), "+f"(c[2]), "+f"(c[3])
        : "r"(a0), "r"(a1), "r"(a2), "r"(a3), "r"(b0), "r"(b1));
}
// permute k-index within 8-groups so (c, c+4) become adjacent -> LDS.64 fragments
__device__ __forceinline__ int kperm(int j) {
    int w = j & 7; return (j & ~7) | ((w & 3) << 1) | (w >> 2);
}

// ---------------- tf32 GEMM: C = A(MxK) @ B(KxN), 128x128x16 tiles ----------------
#define GSTR 24   // smem row stride (floats): 16 data + 8 pad -> conflict-free LDS.64
__global__ __launch_bounds__(256, 2)
void gemm_tf32(const float* __restrict__ A, const float* __restrict__ B,
               float* __restrict__ C, int M, int N, int K)
{
    __shared__ unsigned As[128 * GSTR];   // [m][kperm]
    __shared__ unsigned Bs[128 * GSTR];   // [n][kperm]

    const int tid = threadIdx.x, lane = tid & 31, wid = tid >> 5;
    const int g = lane >> 2, c = lane & 3;
    const int wm = (wid >> 2) * 64, wn = (wid & 3) * 32;
    const size_t bm = (size_t)blockIdx.y * 128, bn = (size_t)blockIdx.x * 128;

    float acc[4][4][4];
#pragma unroll
    for (int i = 0; i < 4; i++)
#pragma unroll
        for (int j = 0; j < 4; j++)
#pragma unroll
            for (int r = 0; r < 4; r++) acc[i][j][r] = 0.f;

    // staging geometry: A tile 128x16 as 512 float4 (f=tid, tid+256)
    const int arow = tid >> 2;           // 0..63
    const int akq  = (tid & 3) * 4;      // k quad
    const int bk0  = tid >> 5;           // 0..7
    const int bn0  = (tid & 31) * 4;

    const int NK = K >> 4;
    float4 sa0, sa1, sb0, sb1;

    // prologue: tile 0
    sa0 = *(const float4*)(A + (bm + arow) * K + akq);
    sa1 = *(const float4*)(A + (bm + arow + 64) * K + akq);
    sb0 = *(const float4*)(B + (size_t)bk0 * N + bn + bn0);
    sb1 = *(const float4*)(B + (size_t)(bk0 + 8) * N + bn + bn0);

#define STORE_A(v, row) do { \
        float vv[4] = {(v).x, (v).y, (v).z, (v).w}; \
        _Pragma("unroll") \
        for (int e = 0; e < 4; e++) As[(row) * GSTR + kperm(akq + e)] = f2tf(vv[e]); \
    } while (0)
#define STORE_B(v, kk) do { \
        float vv[4] = {(v).x, (v).y, (v).z, (v).w}; \
        int kp = kperm(kk); \
        _Pragma("unroll") \
        for (int e = 0; e < 4; e++) Bs[(bn0 + e) * GSTR + kp] = f2tf(vv[e]); \
    } while (0)

    STORE_A(sa0, arow); STORE_A(sa1, arow + 64);
    STORE_B(sb0, bk0);  STORE_B(sb1, bk0 + 8);
    __syncthreads();

    for (int kt = 0; kt < NK; kt++) {
        const bool more = (kt + 1) < NK;
        if (more) {
            const float* Ap = A + bm * K + (kt + 1) * 16;
            sa0 = *(const float4*)(Ap + (size_t)arow * K + akq);
            sa1 = *(const float4*)(Ap + (size_t)(arow + 64) * K + akq);
            const float* Bp = B + (size_t)((kt + 1) * 16) * N + bn;
            sb0 = *(const float4*)(Bp + (size_t)bk0 * N + bn0);
            sb1 = *(const float4*)(Bp + (size_t)(bk0 + 8) * N + bn0);
        }
#pragma unroll
        for (int s = 0; s < 2; s++) {
            unsigned a[4][4], bb[4][2];
#pragma unroll
            for (int mt = 0; mt < 4; mt++) {
                uint2 lo = *(const uint2*)&As[(wm + mt * 16 + g) * GSTR + s * 8 + 2 * c];
                uint2 hi = *(const uint2*)&As[(wm + mt * 16 + g + 8) * GSTR + s * 8 + 2 * c];
                a[mt][0] = lo.x; a[mt][1] = hi.x; a[mt][2] = lo.y; a[mt][3] = hi.y;
            }
#pragma unroll
            for (int nt = 0; nt < 4; nt++) {
                uint2 bv = *(const uint2*)&Bs[(wn + nt * 8 + g) * GSTR + s * 8 + 2 * c];
                bb[nt][0] = bv.x; bb[nt][1] = bv.y;
            }
#pragma unroll
            for (int mt = 0; mt < 4; mt++)
#pragma unroll
                for (int nt = 0; nt < 4; nt++)
                    mma8(acc[mt][nt], a[mt][0], a[mt][1], a[mt][2], a[mt][3],
                         bb[nt][0], bb[nt][1]);
        }
        __syncthreads();
        if (more) {
            STORE_A(sa0, arow); STORE_A(sa1, arow + 64);
            STORE_B(sb0, bk0);  STORE_B(sb1, bk0 + 8);
        }
        __syncthreads();
    }

    // epilogue
#pragma unroll
    for (int mt = 0; mt < 4; mt++) {
        size_t row = bm + wm + mt * 16 + g;
#pragma unroll
        for (int nt = 0; nt < 4; nt++) {
            size_t col = bn + wn + nt * 8 + 2 * c;
            *(float2*)(C + row * N + col)       = make_float2(acc[mt][nt][0], acc[mt][nt][1]);
            *(float2*)(C + (row + 8) * N + col) = make_float2(acc[mt][nt][2], acc[mt][nt][3]);
        }
    }
#undef STORE_A
#undef STORE_B
}

// ---------------- fused per-head RMSNorm + RoPE (unchanged) ----------------
__global__ void rmsnorm_rope_kernel(const float* __restrict__ qkv,
                                    const float* __restrict__ cosb,
                                    const float* __restrict__ sinb,
                                    const float* __restrict__ gq,
                                    const float* __restrict__ gk,
                                    float* __restrict__ qout,
                                    float* __restrict__ kout)
{
    int warp = (blockIdx.x * blockDim.x + threadIdx.x) >> 5;
    int lane = threadIdx.x & 31;
    if (warp >= TOKENS * NHEAD) return;
    int t = warp / NHEAD;
    int h = warp % NHEAD;
    int s = t & (SEQ - 1);
    int b = t / SEQ;

    const float* qp = qkv + (size_t)t * QKVW + h * HDIM;
    const float* kp = qp + HID;

    float q0 = qp[lane], q1 = qp[lane + 32];
    float k0 = kp[lane], k1 = kp[lane + 32];

    float sq = q0 * q0 + q1 * q1;
    float sk = k0 * k0 + k1 * k1;
#pragma unroll
    for (int off = 16; off; off >>= 1) {
        sq += __shfl_xor_sync(0xffffffffu, sq, off);
        sk += __shfl_xor_sync(0xffffffffu, sk, off);
    }
    float rq = rsqrtf(sq * (1.0f / HDIM) + 1e-6f);
    float rk = rsqrtf(sk * (1.0f / HDIM) + 1e-6f);
    q0 *= rq * gq[lane];  q1 *= rq * gq[lane + 32];
    k0 *= rk * gk[lane];  k1 *= rk * gk[lane + 32];

    float c0 = cosb[(size_t)s * HDIM + lane];
    float c1 = cosb[(size_t)s * HDIM + lane + 32];
    float s0 = sinb[(size_t)s * HDIM + lane];
    float s1 = sinb[(size_t)s * HDIM + lane + 32];

    float qo0 = q0 * c0 - q1 * s0;
    float qo1 = q1 * c1 + q0 * s1;
    float ko0 = k0 * c0 - k1 * s0;
    float ko1 = k1 * c1 + k0 * s1;

    size_t base = (((size_t)(b * NHEAD + h)) * SEQ + s) * HDIM;
    qout[base + lane]      = qo0;
    qout[base + lane + 32] = qo1;
    kout[base + lane]      = ko0;
    kout[base + lane + 32] = ko1;
}

// ---------------- causal flash attention, tf32 mma, 128q x 64kv tiles ----------------
#define FSTR 72   // smem row stride (floats), conflict-free for LDS.64 fragments
__global__ __launch_bounds__(256, 1)
void flash_tf32(const float* __restrict__ Q, const float* __restrict__ K,
                const float* __restrict__ qkv, float* __restrict__ O)
{
    extern __shared__ unsigned smx[];
    unsigned* Ks = smx;               // [kv 64][hd perm]   (B-frags for S)
    unsigned* Vs = smx + 64 * FSTR;   // [hd 64][kv perm]   (B-frags for PV)
    unsigned* Ps = smx + 128 * FSTR;  // [q 128][kv perm]   (A-frags for PV)

    const int tid = threadIdx.x, lane = tid & 31, wid = tid >> 5;
    const int g = lane >> 2, c = lane & 3;
    const int qb = blockIdx.x, bh = blockIdx.y;
    const int b = bh >> 4, h = bh & 15;

    const float* Qg = Q + ((size_t)bh * SEQ + qb * 128) * HDIM;
    const float* Kg = K + (size_t)bh * SEQ * HDIM;
    const float* Vg = qkv + (size_t)b * SEQ * QKVW + 2 * HID + h * HDIM;

    // Q fragments (persistent, pre-scaled by 1/sqrt(hd))
    unsigned qf[8][4];
    {
        const float* q0 = Qg + (size_t)(wid * 16 + g) * HDIM;
        const float* q1 = q0 + 8 * HDIM;
#pragma unroll
        for (int s = 0; s < 8; s++) {
            qf[s][0] = f2tf(0.125f * __ldg(q0 + s * 8 + c));
            qf[s][1] = f2tf(0.125f * __ldg(q1 + s * 8 + c));
            qf[s][2] = f2tf(0.125f * __ldg(q0 + s * 8 + c + 4));
            qf[s][3] = f2tf(0.125f * __ldg(q1 + s * 8 + c + 4));
        }
    }

    float oa[8][4];
#pragma unroll
    for (int nt = 0; nt < 8; nt++)
#pragma unroll
        for (int r = 0; r < 4; r++) oa[nt][r] = 0.f;
    float m0 = -INFINITY, m1 = -INFINITY, l0 = 0.f, l1 = 0.f;

    const int lr = tid >> 2;          // loader row 0..63
    const int ld = (tid & 3) * 16;    // loader hd base
    const int vpc = kperm(lr);        // kv storage column for V transpose

    const int ktmax = 2 * qb + 1;
    for (int kt = 0; kt <= ktmax; kt++) {
        __syncthreads();
        // ---- load K tile [kv][hd perm] and V tile transposed [hd][kv perm] ----
        {
            const float* kg = Kg + (size_t)(kt * 64 + lr) * HDIM + ld;
#pragma unroll
            for (int i = 0; i < 16; i += 4) {
                float4 v = *(const float4*)(kg + i);
                float vv[4] = {v.x, v.y, v.z, v.w};
#pragma unroll
                for (int e = 0; e < 4; e++)
                    Ks[lr * FSTR + kperm(ld + i + e)] = f2tf(vv[e]);
            }
            const float* vgp = Vg + (size_t)(kt * 64 + lr) * QKVW + ld;
#pragma unroll
            for (int i = 0; i < 16; i += 4) {
                float4 v = *(const float4*)(vgp + i);
                float vv[4] = {v.x, v.y, v.z, v.w};
#pragma unroll
                for (int e = 0; e < 4; e++)
                    Vs[(ld + i + e) * FSTR + vpc] = f2tf(vv[e]);
            }
        }
        __syncthreads();

        // ---- S = Q K^T (pre-scaled) ----
        float sacc[8][4];
#pragma unroll
        for (int nt = 0; nt < 8; nt++)
#pragma unroll
            for (int r = 0; r < 4; r++) sacc[nt][r] = 0.f;
#pragma unroll
        for (int s = 0; s < 8; s++) {
#pragma unroll
            for (int nt = 0; nt < 8; nt++) {
                uint2 bv = *(const uint2*)&Ks[(nt * 8 + g) * FSTR + s * 8 + 2 * c];
                mma8(sacc[nt], qf[s][0], qf[s][1], qf[s][2], qf[s][3], bv.x, bv.y);
            }
        }

        // ---- causal mask (only last two kv tiles can clip) ----
        if (kt >= 2 * qb) {
            const int row0 = qb * 128 + wid * 16 + g;
#pragma unroll
            for (int nt = 0; nt < 8; nt++) {
                int col = kt * 64 + nt * 8 + 2 * c;
                if (col     > row0)     sacc[nt][0] = -INFINITY;
                if (col + 1 > row0)     sacc[nt][1] = -INFINITY;
                if (col     > row0 + 8) sacc[nt][2] = -INFINITY;
                if (col + 1 > row0 + 8) sacc[nt][3] = -INFINITY;
            }
        }

        // ---- online softmax (2 rows per thread; quad = lanes sharing g) ----
        float rm0 = -INFINITY, rm1 = -INFINITY;
#pragma unroll
        for (int nt = 0; nt < 8; nt++) {
            rm0 = fmaxf(rm0, fmaxf(sacc[nt][0], sacc[nt][1]));
            rm1 = fmaxf(rm1, fmaxf(sacc[nt][2], sacc[nt][3]));
        }
        rm0 = fmaxf(rm0, __shfl_xor_sync(0xffffffffu, rm0, 1));
        rm0 = fmaxf(rm0, __shfl_xor_sync(0xffffffffu, rm0, 2));
        rm1 = fmaxf(rm1, __shfl_xor_sync(0xffffffffu, rm1, 1));
        rm1 = fmaxf(rm1, __shfl_xor_sync(0xffffffffu, rm1, 2));

        float mn0 = fmaxf(m0, rm0), mn1 = fmaxf(m1, rm1);
        float al0 = __expf(m0 - mn0), al1 = __expf(m1 - mn1);
        m0 = mn0; m1 = mn1;
        float s0 = 0.f, s1 = 0.f;
#pragma unroll
        for (int nt = 0; nt < 8; nt++) {
            sacc[nt][0] = __expf(sacc[nt][0] - mn0);
            sacc[nt][1] = __expf(sacc[nt][1] - mn0);
            sacc[nt][2] = __expf(sacc[nt][2] - mn1);
            sacc[nt][3] = __expf(sacc[nt][3] - mn1);
            s0 += sacc[nt][0] + sacc[nt][1];
            s1 += sacc[nt][2] + sacc[nt][3];
        }
        s0 += __shfl_xor_sync(0xffffffffu, s0, 1);
        s0 += __shfl_xor_sync(0xffffffffu, s0, 2);
        s1 += __shfl_xor_sync(0xffffffffu, s1, 1);
        s1 += __shfl_xor_sync(0xffffffffu, s1, 2);
        l0 = l0 * al0 + s0;
        l1 = l1 * al1 + s1;
#pragma unroll
        for (int nt = 0; nt < 8; nt++) {
            oa[nt][0] *= al0; oa[nt][1] *= al0;
            oa[nt][2] *= al1; oa[nt][3] *= al1;
        }

        // ---- P -> smem (warp-private rows), then O += P V ----
        const int prow0 = (wid * 16 + g) * FSTR;
        const int prow1 = prow0 + 8 * FSTR;
#pragma unroll
        for (int nt = 0; nt < 8; nt++) {
            int p0 = kperm(nt * 8 + 2 * c);
            int p1 = kperm(nt * 8 + 2 * c + 1);
            Ps[prow0 + p0] = f2tf(sacc[nt][0]);
            Ps[prow0 + p1] = f2tf(sacc[nt][1]);
            Ps[prow1 + p0] = f2tf(sacc[nt][2]);
            Ps[prow1 + p1] = f2tf(sacc[nt][3]);
        }
        __syncwarp();
#pragma unroll
        for (int s = 0; s < 8; s++) {
            uint2 lo = *(const uint2*)&Ps[prow0 + s * 8 + 2 * c];
            uint2 hi = *(const uint2*)&Ps[prow1 + s * 8 + 2 * c];
#pragma unroll
            for (int nt = 0; nt < 8; nt++) {
                uint2 bv = *(const uint2*)&Vs[(nt * 8 + g) * FSTR + s * 8 + 2 * c];
                mma8(oa[nt], lo.x, hi.x, lo.y, hi.y, bv.x, bv.y);
            }
        }
    }

    // ---- epilogue: normalize, write (B,S,H) ----
    float inv0 = 1.f / l0, inv1 = 1.f / l1;
    const size_t row0 = (size_t)b * SEQ + qb * 128 + wid * 16 + g;
    float* og0 = O + row0 * HID + h * HDIM;
    float* og1 = og0 + 8 * HID;
#pragma unroll
    for (int nt = 0; nt < 8; nt++) {
        int col = nt * 8 + 2 * c;
        *(float2*)(og0 + col) = make_float2(oa[nt][0] * inv0, oa[nt][1] * inv0);
        *(float2*)(og1 + col) = make_float2(oa[nt][2] * inv1, oa[nt][3] * inv1);
    }
}

// ---------------- launch ----------------
extern "C" void kernel_launch(void* const* d_in, const int* in_sizes, int n_in,
                              void* d_out, int out_size)
{
    const float* hs    = (const float*)d_in[0];
    const float* rcos  = (const float*)d_in[1];
    const float* rsin  = (const float*)d_in[2];
    const float* Wqkv  = (const float*)d_in[3];
    const float* Wo    = (const float*)d_in[4];
    const float* gq    = (const float*)d_in[5];
    const float* gk    = (const float*)d_in[6];
    float* out = (float*)d_out;

    float *qkv_p, *q_p, *k_p, *o_p;
    cudaGetSymbolAddress((void**)&qkv_p, g_qkv);
    cudaGetSymbolAddress((void**)&q_p,   g_q);
    cudaGetSymbolAddress((void**)&k_p,   g_k);
    cudaGetSymbolAddress((void**)&o_p,   g_o);

    const int FSMEM = 256 * FSTR * (int)sizeof(float);   // 73728 B
    cudaFuncSetAttribute(flash_tf32, cudaFuncAttributeMaxDynamicSharedMemorySize, FSMEM);

    // 1. QKV = hidden @ W_qkv   (8192x1024 @ 1024x3072)
    gemm_tf32<<<dim3(QKVW / 128, TOKENS / 128), 256>>>(hs, Wqkv, qkv_p, TOKENS, QKVW, HID);
    // 2. RMSNorm + RoPE
    rmsnorm_rope_kernel<<<TOKENS * NHEAD / 8, 256>>>(qkv_p, rcos, rsin, gq, gk, q_p, k_p);
    // 3. causal flash attention (tf32 mma)
    flash_tf32<<<dim3(SEQ / 128, BATCH * NHEAD), 256, FSMEM>>>(q_p, k_p, qkv_p, o_p);
    // 4. out = attn_out @ W_o   (8192x1024 @ 1024x1024)
    gemm_tf32<<<dim3(HID / 128, TOKENS / 128), 256>>>(o_p, Wo, out, TOKENS, HID, HID);
}

// round 7
// speedup vs baseline: 3.2545x; 1.9227x over previous
#include <cuda_runtime.h>
#include <math.h>

// Problem constants: B=2, S=4096, H=1024, NH=16, hd=64
#define BATCH 2
#define SEQ   4096
#define HID   1024
#define NHEAD 16
#define HDIM  64
#define TOKENS (BATCH*SEQ)          // 8192
#define QKVW  (3*HID)               // 3072

// ---------------- device scratch ----------------
__device__ float g_qkv [(size_t)TOKENS * QKVW];   // [t][3H]
__device__ float g_q   [(size_t)TOKENS * HID];    // [bh][s][hd] (tf32-rounded)
__device__ float g_k   [(size_t)TOKENS * HID];    // [bh][s][hd] (tf32-rounded)
__device__ float g_v   [(size_t)TOKENS * HID];    // [bh][hd][s] (tf32-rounded, transposed)
__device__ float g_o   [(size_t)TOKENS * HID];    // [b][s][H]   (tf32-rounded)
__device__ float g_hr  [(size_t)TOKENS * HID];    // hidden rounded
__device__ float g_wqkvT[(size_t)QKVW * HID];     // W_qkv^T rounded  [n][k]
__device__ float g_woT [(size_t)HID * HID];       // W_o^T rounded    [n][k]

// ---------------- helpers ----------------
__device__ __forceinline__ unsigned f2tf(float f) {
    unsigned u; asm("cvt.rna.tf32.f32 %0, %1;" : "=r"(u) : "f"(f)); return u;
}
__device__ __forceinline__ float rtf(float f) { return __uint_as_float(f2tf(f)); }

__device__ __forceinline__ void mma8(float (&c)[4],
                                     unsigned a0, unsigned a1, unsigned a2, unsigned a3,
                                     unsigned b0, unsigned b1) {
    asm volatile(
        "mma.sync.aligned.m16n8k8.row.col.f32.tf32.tf32.f32 "
        "{%0,%1,%2,%3},{%4,%5,%6,%7},{%8,%9},{%0,%1,%2,%3};\n"
        : "+f"(c[0]), "+f"(c[1]), "+f"(c[2]), "+f"(c[3])
        : "r"(a0), "r"(a1), "r"(a2), "r"(a3), "r"(b0), "r"(b1));
}

__device__ __forceinline__ unsigned smem_u32(const void* p) {
    unsigned a;
    asm("{ .reg .u64 t; cvta.to.shared.u64 t, %1; cvt.u32.u64 %0, t; }" : "=r"(a) : "l"(p));
    return a;
}
__device__ __forceinline__ void cp16(unsigned dst, const void* src) {
    asm volatile("cp.async.cg.shared.global [%0], [%1], 16;\n" :: "r"(dst), "l"(src) : "memory");
}
#define CP_COMMIT() asm volatile("cp.async.commit_group;\n" ::: "memory")
#define CP_WAIT(n)  asm volatile("cp.async.wait_group %0;\n" :: "n"(n) : "memory")

// word offset within a row of RW floats (RW = 32 or 64), xor-swizzled at 16B grain
__device__ __forceinline__ int sw(int row, int k, int RW) {
    return row * RW + ((((k >> 2) ^ (row & 7)) << 2) | (k & 3));
}

// ---------------- prep kernels ----------------
__global__ void round_copy(const float* __restrict__ src, float* __restrict__ dst, int n4) {
    int i = blockIdx.x * blockDim.x + threadIdx.x;
    if (i < n4) {
        float4 v = ((const float4*)src)[i];
        v.x = rtf(v.x); v.y = rtf(v.y); v.z = rtf(v.z); v.w = rtf(v.w);
        ((float4*)dst)[i] = v;
    }
}

// dst[c][r] = round(src[r][c]); src R x C, both mult of 32
__global__ void transpose_round(const float* __restrict__ src, float* __restrict__ dst,
                                int R, int C) {
    __shared__ float t[32][33];
    int bx = blockIdx.x * 32, by = blockIdx.y * 32;
    int x = threadIdx.x, y = threadIdx.y;
#pragma unroll
    for (int i = 0; i < 32; i += 8)
        t[y + i][x] = src[(size_t)(by + y + i) * C + bx + x];
    __syncthreads();
#pragma unroll
    for (int i = 0; i < 32; i += 8)
        dst[(size_t)(bx + y + i) * R + by + x] = rtf(t[x][y + i]);
}

// V slice of qkv -> g_v[bh][hd][s], rounded
__global__ void transpose_v(const float* __restrict__ qkv, float* __restrict__ v) {
    __shared__ float t[32][33];
    int bh = blockIdx.z, b = bh >> 4, h = bh & 15;
    const float* src = qkv + (size_t)b * SEQ * QKVW + 2 * HID + h * HDIM;
    float* dst = v + (size_t)bh * HDIM * SEQ;
    int bx = blockIdx.x * 32;   // hd tile
    int by = blockIdx.y * 32;   // s tile
    int x = threadIdx.x, y = threadIdx.y;
#pragma unroll
    for (int i = 0; i < 32; i += 8)
        t[y + i][x] = src[(size_t)(by + y + i) * QKVW + bx + x];
    __syncthreads();
#pragma unroll
    for (int i = 0; i < 32; i += 8)
        dst[(size_t)(bx + y + i) * SEQ + by + x] = rtf(t[x][y + i]);
}

// ---------------- tf32 GEMM, cp.async 3-stage: C = A(MxK) @ Bt(NxK)^T ----------------
#define BK 32
#define GT (128 * BK)        // words per tile
__global__ __launch_bounds__(256, 2)
void gemm_async(const float* __restrict__ A, const float* __restrict__ Bt,
                float* __restrict__ C, int M, int N, int K)
{
    extern __shared__ float sm[];
    float* As = sm;            // [3][128*32]
    float* Bs = sm + 3 * GT;   // [3][128*32]

    const int tid = threadIdx.x, lane = tid & 31, wid = tid >> 5;
    const int g = lane >> 2, c = lane & 3;
    const int wm = (wid >> 2) * 64, wn = (wid & 3) * 32;
    const size_t bm = (size_t)blockIdx.y * 128, bn = (size_t)blockIdx.x * 128;

    const int crow = tid >> 1;            // 0..127
    const int cch  = (tid & 1) * 4;       // chunk 0 or 4 (of 8)
    const unsigned asb = smem_u32(As), bsb = smem_u32(Bs);

    const int NK = K / BK;

    // issue one stage's copies (A tile: 128 rows x 8 chunks; 2 chunks/thread)
    auto issue = [&](int kt, int st) {
        const float* ag = A + (bm + crow) * K + kt * BK;
        const float* bg = Bt + (bn + crow) * K + kt * BK;
#pragma unroll
        for (int j = 0; j < 2; j++) {
            int ch = cch + j;  // wait: cch in {0,4}, chunks per row =8 -> threads pairs cover 0..3 / 4..7
            cp16(asb + (st * GT + sw(crow, ch * 4, BK)) * 4, ag + ch * 4);
            cp16(bsb + (st * GT + sw(crow, ch * 4, BK)) * 4, bg + ch * 4);
            ch += 1; // second chunk
            cp16(asb + (st * GT + sw(crow, ch * 4, BK)) * 4, ag + ch * 4);
            cp16(bsb + (st * GT + sw(crow, ch * 4, BK)) * 4, bg + ch * 4);
            break;
        }
        // cover remaining 2 chunks of this row
        int ch2 = cch + 2;
        cp16(asb + (st * GT + sw(crow, ch2 * 4, BK)) * 4, ag + ch2 * 4);
        cp16(bsb + (st * GT + sw(crow, ch2 * 4, BK)) * 4, bg + ch2 * 4);
        int ch3 = cch + 3;
        cp16(asb + (st * GT + sw(crow, ch3 * 4, BK)) * 4, ag + ch3 * 4);
        cp16(bsb + (st * GT + sw(crow, ch3 * 4, BK)) * 4, bg + ch3 * 4);
    };

    float acc[4][4][4];
#pragma unroll
    for (int i = 0; i < 4; i++)
#pragma unroll
        for (int j = 0; j < 4; j++)
#pragma unroll
            for (int r = 0; r < 4; r++) acc[i][j][r] = 0.f;

    issue(0, 0); CP_COMMIT();
    issue(1, 1); CP_COMMIT();

    for (int kt = 0; kt < NK; kt++) {
        CP_WAIT(1);
        __syncthreads();
        if (kt + 2 < NK) issue(kt + 2, (kt + 2) % 3);
        CP_COMMIT();

        const float* as = As + (kt % 3) * GT;
        const float* bs = Bs + (kt % 3) * GT;
#pragma unroll
        for (int s = 0; s < 4; s++) {
            unsigned a[4][4], bb[4][2];
#pragma unroll
            for (int mt = 0; mt < 4; mt++) {
                int r0 = wm + mt * 16 + g;
                a[mt][0] = __float_as_uint(as[sw(r0,     s * 8 + c,     BK)]);
                a[mt][1] = __float_as_uint(as[sw(r0 + 8, s * 8 + c,     BK)]);
                a[mt][2] = __float_as_uint(as[sw(r0,     s * 8 + c + 4, BK)]);
                a[mt][3] = __float_as_uint(as[sw(r0 + 8, s * 8 + c + 4, BK)]);
            }
#pragma unroll
            for (int nt = 0; nt < 4; nt++) {
                int r0 = wn + nt * 8 + g;
                bb[nt][0] = __float_as_uint(bs[sw(r0, s * 8 + c,     BK)]);
                bb[nt][1] = __float_as_uint(bs[sw(r0, s * 8 + c + 4, BK)]);
            }
#pragma unroll
            for (int mt = 0; mt < 4; mt++)
#pragma unroll
                for (int nt = 0; nt < 4; nt++)
                    mma8(acc[mt][nt], a[mt][0], a[mt][1], a[mt][2], a[mt][3],
                         bb[nt][0], bb[nt][1]);
        }
    }

#pragma unroll
    for (int mt = 0; mt < 4; mt++) {
        size_t row = bm + wm + mt * 16 + g;
#pragma unroll
        for (int nt = 0; nt < 4; nt++) {
            size_t col = bn + wn + nt * 8 + 2 * c;
            *(float2*)(C + row * N + col)       = make_float2(acc[mt][nt][0], acc[mt][nt][1]);
            *(float2*)(C + (row + 8) * N + col) = make_float2(acc[mt][nt][2], acc[mt][nt][3]);
        }
    }
}

// ---------------- RMSNorm + RoPE (emit tf32-rounded q,k) ----------------
__global__ void rmsnorm_rope_kernel(const float* __restrict__ qkv,
                                    const float* __restrict__ cosb,
                                    const float* __restrict__ sinb,
                                    const float* __restrict__ gq,
                                    const float* __restrict__ gk,
                                    float* __restrict__ qout,
                                    float* __restrict__ kout)
{
    int warp = (blockIdx.x * blockDim.x + threadIdx.x) >> 5;
    int lane = threadIdx.x & 31;
    if (warp >= TOKENS * NHEAD) return;
    int t = warp / NHEAD, h = warp % NHEAD;
    int s = t & (SEQ - 1), b = t / SEQ;

    const float* qp = qkv + (size_t)t * QKVW + h * HDIM;
    const float* kp = qp + HID;

    float q0 = qp[lane], q1 = qp[lane + 32];
    float k0 = kp[lane], k1 = kp[lane + 32];

    float sq = q0 * q0 + q1 * q1;
    float sk = k0 * k0 + k1 * k1;
#pragma unroll
    for (int off = 16; off; off >>= 1) {
        sq += __shfl_xor_sync(0xffffffffu, sq, off);
        sk += __shfl_xor_sync(0xffffffffu, sk, off);
    }
    float rq = rsqrtf(sq * (1.0f / HDIM) + 1e-6f);
    float rk = rsqrtf(sk * (1.0f / HDIM) + 1e-6f);
    q0 *= rq * gq[lane];  q1 *= rq * gq[lane + 32];
    k0 *= rk * gk[lane];  k1 *= rk * gk[lane + 32];

    float c0 = cosb[(size_t)s * HDIM + lane];
    float c1 = cosb[(size_t)s * HDIM + lane + 32];
    float s0 = sinb[(size_t)s * HDIM + lane];
    float s1 = sinb[(size_t)s * HDIM + lane + 32];

    size_t base = (((size_t)(b * NHEAD + h)) * SEQ + s) * HDIM;
    qout[base + lane]      = rtf(q0 * c0 - q1 * s0);
    qout[base + lane + 32] = rtf(q1 * c1 + q0 * s1);
    kout[base + lane]      = rtf(k0 * c0 - k1 * s0);
    kout[base + lane + 32] = rtf(k1 * c1 + k0 * s1);
}

// ---------------- causal flash attention, cp.async double-buffered ----------------
#define FT (64 * 64)   // words per K/V tile
__global__ __launch_bounds__(256)
void flash_async(const float* __restrict__ Q, const float* __restrict__ K,
                 const float* __restrict__ V, float* __restrict__ O)
{
    extern __shared__ float sm[];
    float* Ks = sm;             // [2][64*64]  rows=kv, k=hd
    float* Vs = sm + 2 * FT;    // [2][64*64]  rows=hd, k=kv
    float* Ps = sm + 4 * FT;    // [128*64]    rows=q,  k=kv

    const int tid = threadIdx.x, lane = tid & 31, wid = tid >> 5;
    const int g = lane >> 2, c = lane & 3;
    const int qb = (SEQ / 128 - 1) - blockIdx.x;   // descending work size first
    const int bh = blockIdx.y;
    const int b = bh >> 4, h = bh & 15;

    const float* Qg = Q + ((size_t)bh * SEQ + qb * 128) * HDIM;
    const float* Kg = K + (size_t)bh * SEQ * HDIM;
    const float* Vg = V + (size_t)bh * HDIM * SEQ;   // [hd][s]
    const unsigned ksb = smem_u32(Ks), vsb = smem_u32(Vs);

    // persistent Q fragments, pre-scaled
    unsigned qf[8][4];
    {
        const float* q0 = Qg + (size_t)(wid * 16 + g) * HDIM;
        const float* q1 = q0 + 8 * HDIM;
#pragma unroll
        for (int s = 0; s < 8; s++) {
            qf[s][0] = f2tf(0.125f * __ldg(q0 + s * 8 + c));
            qf[s][1] = f2tf(0.125f * __ldg(q1 + s * 8 + c));
            qf[s][2] = f2tf(0.125f * __ldg(q0 + s * 8 + c + 4));
            qf[s][3] = f2tf(0.125f * __ldg(q1 + s * 8 + c + 4));
        }
    }

    // tile copy: 64 rows x 16 chunks each for K and V; 4+4 cp.async per thread
    const int frow = tid >> 2;         // 0..63
    const int fch0 = (tid & 3) * 4;    // chunk base 0,4,8,12
    auto issue = [&](int kt, int buf) {
#pragma unroll
        for (int j = 0; j < 4; j++) {
            int ch = fch0 + j;
            cp16(ksb + (buf * FT + sw(frow, ch * 4, 64)) * 4,
                 Kg + (size_t)(kt * 64 + frow) * HDIM + ch * 4);
            cp16(vsb + (buf * FT + sw(frow, ch * 4, 64)) * 4,
                 Vg + (size_t)frow * SEQ + kt * 64 + ch * 4);
        }
    };

    float oa[8][4];
#pragma unroll
    for (int nt = 0; nt < 8; nt++)
#pragma unroll
        for (int r = 0; r < 4; r++) oa[nt][r] = 0.f;
    float m0 = -INFINITY, m1 = -INFINITY, l0 = 0.f, l1 = 0.f;

    const int ktmax = 2 * qb + 1;
    issue(0, 0); CP_COMMIT();

    for (int kt = 0; kt <= ktmax; kt++) {
        CP_WAIT(0);
        __syncthreads();
        if (kt < ktmax) issue(kt + 1, (kt + 1) & 1);
        CP_COMMIT();

        const float* ks = Ks + (kt & 1) * FT;
        const float* vs = Vs + (kt & 1) * FT;

        // ---- S = Q K^T ----
        float sacc[8][4];
#pragma unroll
        for (int nt = 0; nt < 8; nt++)
#pragma unroll
            for (int r = 0; r < 4; r++) sacc[nt][r] = 0.f;
#pragma unroll
        for (int s = 0; s < 8; s++) {
#pragma unroll
            for (int nt = 0; nt < 8; nt++) {
                unsigned b0 = __float_as_uint(ks[sw(nt * 8 + g, s * 8 + c,     64)]);
                unsigned b1 = __float_as_uint(ks[sw(nt * 8 + g, s * 8 + c + 4, 64)]);
                mma8(sacc[nt], qf[s][0], qf[s][1], qf[s][2], qf[s][3], b0, b1);
            }
        }

        // ---- causal mask ----
        if (kt >= 2 * qb) {
            const int row0 = qb * 128 + wid * 16 + g;
#pragma unroll
            for (int nt = 0; nt < 8; nt++) {
                int col = kt * 64 + nt * 8 + 2 * c;
                if (col     > row0)     sacc[nt][0] = -INFINITY;
                if (col + 1 > row0)     sacc[nt][1] = -INFINITY;
                if (col     > row0 + 8) sacc[nt][2] = -INFINITY;
                if (col + 1 > row0 + 8) sacc[nt][3] = -INFINITY;
            }
        }

        // ---- online softmax ----
        float rm0 = -INFINITY, rm1 = -INFINITY;
#pragma unroll
        for (int nt = 0; nt < 8; nt++) {
            rm0 = fmaxf(rm0, fmaxf(sacc[nt][0], sacc[nt][1]));
            rm1 = fmaxf(rm1, fmaxf(sacc[nt][2], sacc[nt][3]));
        }
        rm0 = fmaxf(rm0, __shfl_xor_sync(0xffffffffu, rm0, 1));
        rm0 = fmaxf(rm0, __shfl_xor_sync(0xffffffffu, rm0, 2));
        rm1 = fmaxf(rm1, __shfl_xor_sync(0xffffffffu, rm1, 1));
        rm1 = fmaxf(rm1, __shfl_xor_sync(0xffffffffu, rm1, 2));

        float mn0 = fmaxf(m0, rm0), mn1 = fmaxf(m1, rm1);
        float al0 = __expf(m0 - mn0), al1 = __expf(m1 - mn1);
        m0 = mn0; m1 = mn1;
        float s0 = 0.f, s1 = 0.f;
#pragma unroll
        for (int nt = 0; nt < 8; nt++) {
            sacc[nt][0] = __expf(sacc[nt][0] - mn0);
            sacc[nt][1] = __expf(sacc[nt][1] - mn0);
            sacc[nt][2] = __expf(sacc[nt][2] - mn1);
            sacc[nt][3] = __expf(sacc[nt][3] - mn1);
            s0 += sacc[nt][0] + sacc[nt][1];
            s1 += sacc[nt][2] + sacc[nt][3];
        }
        s0 += __shfl_xor_sync(0xffffffffu, s0, 1);
        s0 += __shfl_xor_sync(0xffffffffu, s0, 2);
        s1 += __shfl_xor_sync(0xffffffffu, s1, 1);
        s1 += __shfl_xor_sync(0xffffffffu, s1, 2);
        l0 = l0 * al0 + s0;
        l1 = l1 * al1 + s1;
#pragma unroll
        for (int nt = 0; nt < 8; nt++) {
            oa[nt][0] *= al0; oa[nt][1] *= al0;
            oa[nt][2] *= al1; oa[nt][3] *= al1;
        }

        // ---- P -> smem (warp-private rows), then O += P V ----
        const int pr0 = wid * 16 + g, pr1 = pr0 + 8;
#pragma unroll
        for (int nt = 0; nt < 8; nt++) {
            int k0 = nt * 8 + 2 * c;
            *(float2*)&Ps[sw(pr0, k0, 64)] =
                make_float2(__uint_as_float(f2tf(sacc[nt][0])), __uint_as_float(f2tf(sacc[nt][1])));
            *(float2*)&Ps[sw(pr1, k0, 64)] =
                make_float2(__uint_as_float(f2tf(sacc[nt][2])), __uint_as_float(f2tf(sacc[nt][3])));
        }
        __syncwarp();
#pragma unroll
        for (int s = 0; s < 8; s++) {
            unsigned a0 = __float_as_uint(Ps[sw(pr0, s * 8 + c,     64)]);
            unsigned a1 = __float_as_uint(Ps[sw(pr1, s * 8 + c,     64)]);
            unsigned a2 = __float_as_uint(Ps[sw(pr0, s * 8 + c + 4, 64)]);
            unsigned a3 = __float_as_uint(Ps[sw(pr1, s * 8 + c + 4, 64)]);
#pragma unroll
            for (int nt = 0; nt < 8; nt++) {
                unsigned b0 = __float_as_uint(vs[sw(nt * 8 + g, s * 8 + c,     64)]);
                unsigned b1 = __float_as_uint(vs[sw(nt * 8 + g, s * 8 + c + 4, 64)]);
                mma8(oa[nt], a0, a1, a2, a3, b0, b1);
            }
        }
    }

    // ---- epilogue: normalize, round, write (B,S,H) ----
    float inv0 = 1.f / l0, inv1 = 1.f / l1;
    const size_t row0 = (size_t)b * SEQ + qb * 128 + wid * 16 + g;
    float* og0 = O + row0 * HID + h * HDIM;
    float* og1 = og0 + 8 * HID;
#pragma unroll
    for (int nt = 0; nt < 8; nt++) {
        int col = nt * 8 + 2 * c;
        *(float2*)(og0 + col) = make_float2(rtf(oa[nt][0] * inv0), rtf(oa[nt][1] * inv0));
        *(float2*)(og1 + col) = make_float2(rtf(oa[nt][2] * inv1), rtf(oa[nt][3] * inv1));
    }
}

// ---------------- launch ----------------
extern "C" void kernel_launch(void* const* d_in, const int* in_sizes, int n_in,
                              void* d_out, int out_size)
{
    const float* hs    = (const float*)d_in[0];
    const float* rcos  = (const float*)d_in[1];
    const float* rsin  = (const float*)d_in[2];
    const float* Wqkv  = (const float*)d_in[3];
    const float* Wo    = (const float*)d_in[4];
    const float* gq    = (const float*)d_in[5];
    const float* gk    = (const float*)d_in[6];
    float* out = (float*)d_out;

    float *qkv_p, *q_p, *k_p, *v_p, *o_p, *hr_p, *wqkvT_p, *woT_p;
    cudaGetSymbolAddress((void**)&qkv_p,   g_qkv);
    cudaGetSymbolAddress((void**)&q_p,     g_q);
    cudaGetSymbolAddress((void**)&k_p,     g_k);
    cudaGetSymbolAddress((void**)&v_p,     g_v);
    cudaGetSymbolAddress((void**)&o_p,     g_o);
    cudaGetSymbolAddress((void**)&hr_p,    g_hr);
    cudaGetSymbolAddress((void**)&wqkvT_p, g_wqkvT);
    cudaGetSymbolAddress((void**)&woT_p,   g_woT);

    const int GSMEM = 6 * GT * (int)sizeof(float);   // 98304
    const int FSMEM = (4 * FT + 128 * 64) * (int)sizeof(float);  // 98304
    cudaFuncSetAttribute(gemm_async,  cudaFuncAttributeMaxDynamicSharedMemorySize, GSMEM);
    cudaFuncSetAttribute(flash_async, cudaFuncAttributeMaxDynamicSharedMemorySize, FSMEM);

    // prep: round/transpose operands
    round_copy<<<(TOKENS * HID / 4 + 255) / 256, 256>>>(hs, hr_p, TOKENS * HID / 4);
    transpose_round<<<dim3(QKVW / 32, HID / 32), dim3(32, 8)>>>(Wqkv, wqkvT_p, HID, QKVW);
    transpose_round<<<dim3(HID / 32, HID / 32), dim3(32, 8)>>>(Wo, woT_p, HID, HID);

    // 1. QKV = hidden @ W_qkv
    gemm_async<<<dim3(QKVW / 128, TOKENS / 128), 256, GSMEM>>>(hr_p, wqkvT_p, qkv_p,
                                                               TOKENS, QKVW, HID);
    // 2. RMSNorm + RoPE -> rounded q,k
    rmsnorm_rope_kernel<<<TOKENS * NHEAD / 8, 256>>>(qkv_p, rcos, rsin, gq, gk, q_p, k_p);
    // 2b. V -> [bh][hd][s] rounded
    transpose_v<<<dim3(HDIM / 32, SEQ / 32, BATCH * NHEAD), dim3(32, 8)>>>(qkv_p, v_p);
    // 3. causal flash attention
    flash_async<<<dim3(SEQ / 128, BATCH * NHEAD), 256, FSMEM>>>(q_p, k_p, v_p, o_p);
    // 4. out = attn_out @ W_o
    gemm_async<<<dim3(HID / 128, TOKENS / 128), 256, GSMEM>>>(o_p, woT_p, out,
                                                              TOKENS, HID, HID);
}

// round 10
// speedup vs baseline: 3.8972x; 1.1975x over previous
#include <cuda_runtime.h>
#include <math.h>
#include <stdint.h>

// Problem constants: B=2, S=4096, H=1024, NH=16, hd=64
#define BATCH 2
#define SEQ   4096
#define HID   1024
#define NHEAD 16
#define HDIM  64
#define TOKENS (BATCH*SEQ)          // 8192
#define QKVW  (3*HID)               // 3072

// ---------------- device scratch ----------------
__device__ float g_qkv  [(size_t)TOKENS * QKVW];  // QKV gemm output, normal [t][3H]
__device__ float g_apk  [(size_t)TOKENS * HID];   // hidden, packed for gemm
__device__ float g_q    [(size_t)TOKENS * HID];   // [bh][s][hd] normal, tf32-rounded
__device__ float g_kpk  [(size_t)TOKENS * HID];   // K packed for flash tiles
__device__ float g_vpk  [(size_t)TOKENS * HID];   // V packed for flash tiles ([hd][kv])
__device__ float g_opk  [(size_t)TOKENS * HID];   // attn out, packed for out-gemm
__device__ float g_wqkv_pk[(size_t)QKVW * HID];   // W_qkv^T packed
__device__ float g_wo_pk  [(size_t)HID * HID];    // W_o^T packed

// ---------------- tf32 / layout helpers ----------------
__device__ __forceinline__ unsigned f2tf(float f) {
    unsigned u; asm("cvt.rna.tf32.f32 %0, %1;" : "=r"(u) : "f"(f)); return u;
}
__device__ __forceinline__ float rtf(float f) { return __uint_as_float(f2tf(f)); }

__device__ __forceinline__ void mma8(float (&c)[4],
                                     unsigned a0, unsigned a1, unsigned a2, unsigned a3,
                                     unsigned b0, unsigned b1) {
    asm volatile(
        "mma.sync.aligned.m16n8k8.row.col.f32.tf32.tf32.f32 "
        "{%0,%1,%2,%3},{%4,%5,%6,%7},{%8,%9},{%0,%1,%2,%3};\n"
        : "+f"(c[0]), "+f"(c[1]), "+f"(c[2]), "+f"(c[3])
        : "r"(a0), "r"(a1), "r"(a2), "r"(a3), "r"(b0), "r"(b1));
}

__device__ __forceinline__ unsigned smem_u32(const void* p) {
    unsigned a;
    asm("{ .reg .u64 t; cvta.to.shared.u64 t, %1; cvt.u32.u64 %0, t; }" : "=r"(a) : "l"(p));
    return a;
}
__device__ __forceinline__ void cp16(unsigned dst, const void* src) {
    asm volatile("cp.async.cg.shared.global [%0], [%1], 16;\n" :: "r"(dst), "l"(src) : "memory");
}
#define CP_COMMIT() asm volatile("cp.async.commit_group;\n" ::: "memory")
#define CP_WAIT(n)  asm volatile("cp.async.wait_group %0;\n" :: "n"(n) : "memory")

// k-permutation within 8-groups: (c, c+4) become adjacent -> LDS.64 fragments
__device__ __forceinline__ int pk8(int k) {
    return (k & ~7) | ((k & 3) << 1) | ((k >> 2) & 1);
}
// 32B-group xor swizzle (conflict-free per half-warp phase for all fragment loads)
__device__ __forceinline__ int swp32(int row, int p) {   // row of 32 floats (GEMM)
    return row * 32 + ((((p >> 3) ^ (row & 3)) << 3) | (p & 7));
}
__device__ __forceinline__ int swp64(int row, int p) {   // row of 64 floats (flash)
    return row * 64 + ((((p >> 3) ^ (row & 7)) << 3) | (p & 7));
}

// ---------------- prep kernels ----------------
// pack A [rows][K] -> blocks of (128 rows x 32 k) in smem image, tf32-rounded
__global__ void pack_a(const float* __restrict__ src, float* __restrict__ dst, int K) {
    int i = blockIdx.x * blockDim.x + threadIdx.x;   // float4 id, exact grid
    int kq = K >> 2;
    int row = i / kq, k = (i - row * kq) * 4;
    float4 v = ((const float4*)src)[i];
    size_t blk = ((size_t)(row >> 7) * (K >> 5) + (k >> 5)) * 4096;
    int r = row & 127, kc = k & 31;
    float vv[4] = {v.x, v.y, v.z, v.w};
#pragma unroll
    for (int e = 0; e < 4; e++)
        dst[blk + swp32(r, pk8(kc + e))] = rtf(vv[e]);
}

// W [K][N] -> W^T packed blocks (rows = n), tf32-rounded
__global__ void pack_wT(const float* __restrict__ src, float* __restrict__ dst,
                        int K, int N) {
    __shared__ float t[32][33];
    int bn = blockIdx.x * 32, bk = blockIdx.y * 32;
    int x = threadIdx.x, y = threadIdx.y;
#pragma unroll
    for (int i = 0; i < 32; i += 8)
        t[y + i][x] = src[(size_t)(bk + y + i) * N + bn + x];   // t[k_loc][n_loc]
    __syncthreads();
#pragma unroll
    for (int i = 0; i < 32; i += 8) {
        int n = bn + y + i, k = bk + x;
        size_t blk = ((size_t)(n >> 7) * (K >> 5) + (k >> 5)) * 4096;
        dst[blk + swp32(n & 127, pk8(k & 31))] = rtf(t[x][y + i]);
    }
}

// V slice of qkv -> packed flash tiles [bh][kvtile][hd row 64][kv 64], rounded
__global__ void pack_v(const float* __restrict__ qkv, float* __restrict__ v) {
    __shared__ float t[32][33];
    int bh = blockIdx.z, b = bh >> 4, h = bh & 15;
    const float* src = qkv + (size_t)b * SEQ * QKVW + 2 * HID + h * HDIM;
    int bx = blockIdx.x * 32;   // hd tile
    int by = blockIdx.y * 32;   // s tile
    int x = threadIdx.x, y = threadIdx.y;
#pragma unroll
    for (int i = 0; i < 32; i += 8)
        t[y + i][x] = src[(size_t)(by + y + i) * QKVW + bx + x];   // t[s_loc][hd_loc]
    __syncthreads();
#pragma unroll
    for (int i = 0; i < 32; i += 8) {
        int hd = bx + y + i, s = by + x;
        size_t blk = ((size_t)bh * (SEQ >> 6) + (s >> 6)) * 4096;
        v[blk + swp64(hd, pk8(s & 63))] = rtf(t[x][y + i]);
    }
}

// ---------------- RMSNorm + RoPE: q normal, k packed for flash ----------------
__global__ void rmsnorm_rope_kernel(const float* __restrict__ qkv,
                                    const float* __restrict__ cosb,
                                    const float* __restrict__ sinb,
                                    const float* __restrict__ gq,
                                    const float* __restrict__ gk,
                                    float* __restrict__ qout,
                                    float* __restrict__ kout)
{
    int warp = (blockIdx.x * blockDim.x + threadIdx.x) >> 5;
    int lane = threadIdx.x & 31;
    if (warp >= TOKENS * NHEAD) return;
    int t = warp / NHEAD, h = warp % NHEAD;
    int s = t & (SEQ - 1), b = t / SEQ;
    int bh = b * NHEAD + h;

    const float* qp = qkv + (size_t)t * QKVW + h * HDIM;
    const float* kp = qp + HID;

    float q0 = qp[lane], q1 = qp[lane + 32];
    float k0 = kp[lane], k1 = kp[lane + 32];

    float sq = q0 * q0 + q1 * q1;
    float sk = k0 * k0 + k1 * k1;
#pragma unroll
    for (int off = 16; off; off >>= 1) {
        sq += __shfl_xor_sync(0xffffffffu, sq, off);
        sk += __shfl_xor_sync(0xffffffffu, sk, off);
    }
    float rq = rsqrtf(sq * (1.0f / HDIM) + 1e-6f);
    float rk = rsqrtf(sk * (1.0f / HDIM) + 1e-6f);
    q0 *= rq * gq[lane];  q1 *= rq * gq[lane + 32];
    k0 *= rk * gk[lane];  k1 *= rk * gk[lane + 32];

    float c0 = cosb[(size_t)s * HDIM + lane];
    float c1 = cosb[(size_t)s * HDIM + lane + 32];
    float s0 = sinb[(size_t)s * HDIM + lane];
    float s1 = sinb[(size_t)s * HDIM + lane + 32];

    size_t qb = ((size_t)bh * SEQ + s) * HDIM;
    qout[qb + lane]      = rtf(q0 * c0 - q1 * s0);
    qout[qb + lane + 32] = rtf(q1 * c1 + q0 * s1);

    size_t kblk = ((size_t)bh * (SEQ >> 6) + (s >> 6)) * 4096;
    int r = s & 63;
    kout[kblk + swp64(r, pk8(lane))]      = rtf(k0 * c0 - k1 * s0);
    kout[kblk + swp64(r, pk8(lane + 32))] = rtf(k1 * c1 + k0 * s1);
}

// ============ tf32 HMMA GEMM on packed operands: C = A @ B^T, 128x128x32 ============
#define GS 3
#define STW 8192   // words per stage (A 4096 + B 4096)
__global__ __launch_bounds__(256, 2)
void gemm_mma(const float* __restrict__ Apk, const float* __restrict__ Bpk,
              float* __restrict__ C, int M, int N, int K)
{
    extern __shared__ float smf[];
    const int tid = threadIdx.x, lane = tid & 31, wid = tid >> 5;
    const int g = lane >> 2, c = lane & 3;
    const int wm = (wid >> 2) * 64, wn = (wid & 3) * 32;
    const size_t bm = (size_t)blockIdx.y * 128, bn = (size_t)blockIdx.x * 128;
    const int NK = K >> 5;
    const float* ag = Apk + (size_t)blockIdx.y * NK * 4096;
    const float* bg = Bpk + (size_t)blockIdx.x * NK * 4096;
    const unsigned sb = smem_u32(smf);

    auto issue = [&](int kt, int st) {
        const float* a = ag + (size_t)kt * 4096;
        const float* b = bg + (size_t)kt * 4096;
        const unsigned d = sb + st * (STW * 4);
#pragma unroll
        for (int j = 0; j < 4; j++) {
            int ci = tid + 256 * j;
            cp16(d + ci * 16, a + ci * 4);
            cp16(d + 16384 + ci * 16, b + ci * 4);
        }
    };

    float acc[4][4][4];
#pragma unroll
    for (int i = 0; i < 4; i++)
#pragma unroll
        for (int j = 0; j < 4; j++)
#pragma unroll
            for (int r = 0; r < 4; r++) acc[i][j][r] = 0.f;

    issue(0, 0); CP_COMMIT();
    issue(1, 1); CP_COMMIT();

    for (int kt = 0; kt < NK; kt++) {
        CP_WAIT(1);
        __syncthreads();
        if (kt + 2 < NK) issue(kt + 2, (kt + 2) % 3);
        CP_COMMIT();

        const float* as = smf + (kt % 3) * STW;
        const float* bs = as + 4096;
#pragma unroll
        for (int s = 0; s < 4; s++) {
            uint2 al[4], ah[4], bv[4];
#pragma unroll
            for (int mt = 0; mt < 4; mt++) {
                al[mt] = *(const uint2*)&as[swp32(wm + mt * 16 + g,     s * 8 + 2 * c)];
                ah[mt] = *(const uint2*)&as[swp32(wm + mt * 16 + g + 8, s * 8 + 2 * c)];
            }
#pragma unroll
            for (int nt = 0; nt < 4; nt++)
                bv[nt] = *(const uint2*)&bs[swp32(wn + nt * 8 + g, s * 8 + 2 * c)];
#pragma unroll
            for (int mt = 0; mt < 4; mt++)
#pragma unroll
                for (int nt = 0; nt < 4; nt++)
                    mma8(acc[mt][nt], al[mt].x, ah[mt].x, al[mt].y, ah[mt].y,
                         bv[nt].x, bv[nt].y);
        }
    }

#pragma unroll
    for (int mt = 0; mt < 4; mt++) {
        size_t row = bm + wm + mt * 16 + g;
#pragma unroll
        for (int nt = 0; nt < 4; nt++) {
            size_t col = bn + wn + nt * 8 + 2 * c;
            *(float2*)(C + row * N + col)       = make_float2(acc[mt][nt][0], acc[mt][nt][1]);
            *(float2*)(C + (row + 8) * N + col) = make_float2(acc[mt][nt][2], acc[mt][nt][3]);
        }
    }
}

// ---------------- causal flash attention, packed tiles + cp.async ----------------
// smem words: K 2x4096 | V 2x4096 | P 8192  = 24576 (96KB)
__global__ __launch_bounds__(256)
void flash_mma(const float* __restrict__ Q, const float* __restrict__ Kpk,
               const float* __restrict__ Vpk, float* __restrict__ Opk)
{
    extern __shared__ float sm[];
    float* Ksm = sm;            // [2][64*64]
    float* Vsm = sm + 8192;     // [2][64*64]
    float* Ps  = sm + 16384;    // [128*64]

    const int tid = threadIdx.x, lane = tid & 31, wid = tid >> 5;
    const int g = lane >> 2, c = lane & 3;
    const int qb = (SEQ / 128 - 1) - blockIdx.x;
    const int bh = blockIdx.y;
    const int b = bh >> 4, h = bh & 15;

    const float* Qg = Q + ((size_t)bh * SEQ + qb * 128) * HDIM;
    const float* Kg = Kpk + (size_t)bh * (SEQ >> 6) * 4096;
    const float* Vg = Vpk + (size_t)bh * (SEQ >> 6) * 4096;
    const unsigned ksb = smem_u32(Ksm), vsb = smem_u32(Vsm);

    // persistent Q fragments, pre-scaled by 1/sqrt(hd)
    unsigned qf[8][4];
    {
        const float* q0 = Qg + (size_t)(wid * 16 + g) * HDIM;
        const float* q1 = q0 + 8 * HDIM;
#pragma unroll
        for (int s = 0; s < 8; s++) {
            qf[s][0] = f2tf(0.125f * __ldg(q0 + s * 8 + c));
            qf[s][1] = f2tf(0.125f * __ldg(q1 + s * 8 + c));
            qf[s][2] = f2tf(0.125f * __ldg(q0 + s * 8 + c + 4));
            qf[s][3] = f2tf(0.125f * __ldg(q1 + s * 8 + c + 4));
        }
    }

    auto issue = [&](int kt, int buf) {
        const float* kg = Kg + (size_t)kt * 4096;
        const float* vg = Vg + (size_t)kt * 4096;
#pragma unroll
        for (int j = 0; j < 4; j++) {
            int ci = tid + 256 * j;
            cp16(ksb + buf * 16384 + ci * 16, kg + ci * 4);
            cp16(vsb + buf * 16384 + ci * 16, vg + ci * 4);
        }
    };

    float oa[8][4];
#pragma unroll
    for (int nt = 0; nt < 8; nt++)
#pragma unroll
        for (int r = 0; r < 4; r++) oa[nt][r] = 0.f;
    float m0 = -INFINITY, m1 = -INFINITY, l0 = 0.f, l1 = 0.f;

    const int ktmax = 2 * qb + 1;
    issue(0, 0); CP_COMMIT();

    for (int kt = 0; kt <= ktmax; kt++) {
        CP_WAIT(0);
        __syncthreads();
        if (kt < ktmax) issue(kt + 1, (kt + 1) & 1);
        CP_COMMIT();

        const float* ks = Ksm + (kt & 1) * 4096;
        const float* vs = Vsm + (kt & 1) * 4096;

        // ---- S = Q K^T ----
        float sacc[8][4];
#pragma unroll
        for (int nt = 0; nt < 8; nt++)
#pragma unroll
            for (int r = 0; r < 4; r++) sacc[nt][r] = 0.f;
#pragma unroll
        for (int s = 0; s < 8; s++) {
#pragma unroll
            for (int nt = 0; nt < 8; nt++) {
                uint2 bv = *(const uint2*)&ks[swp64(nt * 8 + g, s * 8 + 2 * c)];
                mma8(sacc[nt], qf[s][0], qf[s][1], qf[s][2], qf[s][3], bv.x, bv.y);
            }
        }

        // ---- causal mask ----
        if (kt >= 2 * qb) {
            const int row0 = qb * 128 + wid * 16 + g;
#pragma unroll
            for (int nt = 0; nt < 8; nt++) {
                int col = kt * 64 + nt * 8 + 2 * c;
                if (col     > row0)     sacc[nt][0] = -INFINITY;
                if (col + 1 > row0)     sacc[nt][1] = -INFINITY;
                if (col     > row0 + 8) sacc[nt][2] = -INFINITY;
                if (col + 1 > row0 + 8) sacc[nt][3] = -INFINITY;
            }
        }

        // ---- online softmax ----
        float rm0 = -INFINITY, rm1 = -INFINITY;
#pragma unroll
        for (int nt = 0; nt < 8; nt++) {
            rm0 = fmaxf(rm0, fmaxf(sacc[nt][0], sacc[nt][1]));
            rm1 = fmaxf(rm1, fmaxf(sacc[nt][2], sacc[nt][3]));
        }
        rm0 = fmaxf(rm0, __shfl_xor_sync(0xffffffffu, rm0, 1));
        rm0 = fmaxf(rm0, __shfl_xor_sync(0xffffffffu, rm0, 2));
        rm1 = fmaxf(rm1, __shfl_xor_sync(0xffffffffu, rm1, 1));
        rm1 = fmaxf(rm1, __shfl_xor_sync(0xffffffffu, rm1, 2));

        float mn0 = fmaxf(m0, rm0), mn1 = fmaxf(m1, rm1);
        float al0 = __expf(m0 - mn0), al1 = __expf(m1 - mn1);
        m0 = mn0; m1 = mn1;
        float s0 = 0.f, s1 = 0.f;
#pragma unroll
        for (int nt = 0; nt < 8; nt++) {
            sacc[nt][0] = __expf(sacc[nt][0] - mn0);
            sacc[nt][1] = __expf(sacc[nt][1] - mn0);
            sacc[nt][2] = __expf(sacc[nt][2] - mn1);
            sacc[nt][3] = __expf(sacc[nt][3] - mn1);
            s0 += sacc[nt][0] + sacc[nt][1];
            s1 += sacc[nt][2] + sacc[nt][3];
        }
        s0 += __shfl_xor_sync(0xffffffffu, s0, 1);
        s0 += __shfl_xor_sync(0xffffffffu, s0, 2);
        s1 += __shfl_xor_sync(0xffffffffu, s1, 1);
        s1 += __shfl_xor_sync(0xffffffffu, s1, 2);
        l0 = l0 * al0 + s0;
        l1 = l1 * al1 + s1;
#pragma unroll
        for (int nt = 0; nt < 8; nt++) {
            oa[nt][0] *= al0; oa[nt][1] *= al0;
            oa[nt][2] *= al1; oa[nt][3] *= al1;
        }

        // ---- P -> smem (packed positions), then O += P V ----
        const int pr0 = wid * 16 + g, pr1 = pr0 + 8;
#pragma unroll
        for (int nt = 0; nt < 8; nt++) {
            int p0 = pk8(nt * 8 + 2 * c);
            int p1 = pk8(nt * 8 + 2 * c + 1);
            Ps[swp64(pr0, p0)] = __uint_as_float(f2tf(sacc[nt][0]));
            Ps[swp64(pr0, p1)] = __uint_as_float(f2tf(sacc[nt][1]));
            Ps[swp64(pr1, p0)] = __uint_as_float(f2tf(sacc[nt][2]));
            Ps[swp64(pr1, p1)] = __uint_as_float(f2tf(sacc[nt][3]));
        }
        __syncwarp();
#pragma unroll
        for (int s = 0; s < 8; s++) {
            uint2 lo = *(const uint2*)&Ps[swp64(pr0, s * 8 + 2 * c)];
            uint2 hi = *(const uint2*)&Ps[swp64(pr1, s * 8 + 2 * c)];
#pragma unroll
            for (int nt = 0; nt < 8; nt++) {
                uint2 bv = *(const uint2*)&vs[swp64(nt * 8 + g, s * 8 + 2 * c)];
                mma8(oa[nt], lo.x, hi.x, lo.y, hi.y, bv.x, bv.y);
            }
        }
    }

    // ---- epilogue: normalize, write PACKED for the output GEMM ----
    float inv0 = 1.f / l0, inv1 = 1.f / l1;
    const int rr0 = wid * 16 + g;                 // row within 128-token tile
    const size_t obase = ((size_t)(b * 32 + qb) * 32) * 4096;  // (row>>7)*(HID/32) blocks
#pragma unroll
    for (int nt = 0; nt < 8; nt++) {
        int cl = nt * 8 + 2 * c;
        int k = h * 64 + cl;
        size_t blk = obase + (size_t)(k >> 5) * 4096;
        int kc = k & 31;
        Opk[blk + swp32(rr0,     pk8(kc))]     = rtf(oa[nt][0] * inv0);
        Opk[blk + swp32(rr0,     pk8(kc + 1))] = rtf(oa[nt][1] * inv0);
        Opk[blk + swp32(rr0 + 8, pk8(kc))]     = rtf(oa[nt][2] * inv1);
        Opk[blk + swp32(rr0 + 8, pk8(kc + 1))] = rtf(oa[nt][3] * inv1);
    }
}

// ---------------- launch ----------------
extern "C" void kernel_launch(void* const* d_in, const int* in_sizes, int n_in,
                              void* d_out, int out_size)
{
    const float* hs    = (const float*)d_in[0];
    const float* rcos  = (const float*)d_in[1];
    const float* rsin  = (const float*)d_in[2];
    const float* Wqkv  = (const float*)d_in[3];
    const float* Wo    = (const float*)d_in[4];
    const float* gq    = (const float*)d_in[5];
    const float* gk    = (const float*)d_in[6];
    float* out = (float*)d_out;

    float *qkv_p, *apk_p, *q_p, *kpk_p, *vpk_p, *opk_p, *wqkv_p, *wo_p;
    cudaGetSymbolAddress((void**)&qkv_p,  g_qkv);
    cudaGetSymbolAddress((void**)&apk_p,  g_apk);
    cudaGetSymbolAddress((void**)&q_p,    g_q);
    cudaGetSymbolAddress((void**)&kpk_p,  g_kpk);
    cudaGetSymbolAddress((void**)&vpk_p,  g_vpk);
    cudaGetSymbolAddress((void**)&opk_p,  g_opk);
    cudaGetSymbolAddress((void**)&wqkv_p, g_wqkv_pk);
    cudaGetSymbolAddress((void**)&wo_p,   g_wo_pk);

    const int GSMEM = GS * STW * (int)sizeof(float);          // 98304
    const int FSMEM = 24576 * (int)sizeof(float);             // 98304
    cudaFuncSetAttribute(gemm_mma,  cudaFuncAttributeMaxDynamicSharedMemorySize, GSMEM);
    cudaFuncSetAttribute(flash_mma, cudaFuncAttributeMaxDynamicSharedMemorySize, FSMEM);

    // prep: pack operands into mma-ready global layouts (tf32-rounded)
    pack_a<<<TOKENS * HID / 4 / 256, 256>>>(hs, apk_p, HID);
    pack_wT<<<dim3(QKVW / 32, HID / 32), dim3(32, 8)>>>(Wqkv, wqkv_p, HID, QKVW);
    pack_wT<<<dim3(HID / 32, HID / 32), dim3(32, 8)>>>(Wo, wo_p, HID, HID);

    // 1. QKV = hidden @ W_qkv
    gemm_mma<<<dim3(QKVW / 128, TOKENS / 128), 256, GSMEM>>>(apk_p, wqkv_p, qkv_p,
                                                             TOKENS, QKVW, HID);
    // 2. RMSNorm + RoPE (q normal, k packed)
    rmsnorm_rope_kernel<<<TOKENS * NHEAD / 8, 256>>>(qkv_p, rcos, rsin, gq, gk, q_p, kpk_p);
    // 2b. V -> packed flash tiles
    pack_v<<<dim3(HDIM / 32, SEQ / 32, BATCH * NHEAD), dim3(32, 8)>>>(qkv_p, vpk_p);
    // 3. causal flash attention (writes packed attn-out)
    flash_mma<<<dim3(SEQ / 128, BATCH * NHEAD), 256, FSMEM>>>(q_p, kpk_p, vpk_p, opk_p);
    // 4. out = attn_out @ W_o
    gemm_mma<<<dim3(HID / 128, TOKENS / 128), 256, GSMEM>>>(opk_p, wo_p, out,
                                                            TOKENS, HID, HID);
}